// round 12
// baseline (speedup 1.0000x reference)
#include <cuda_runtime.h>
#include <math.h>

#define T_ 2000
#define B_ 64
#define H_ 512
#define TB_ (T_*B_)

// ---- scratch ----
__device__ float g_wh[TB_*H_];
__device__ float g_wz[TB_*H_];
__device__ float g_h1[TB_*H_];
__device__ float g_hT[8*8*512];      // [group][b][512 j]
__device__ float g_zhT[8*8*512];     // [group][b][512 j]
__device__ unsigned int g_flags[8*16];   // per-CTA monotonic flags, 64B/group

// =====================================================================
// bf16 split helpers (shared by proj + scan) — proven in rounds 8-11
// word packs: even elem -> low 16, odd elem -> high 16
// =====================================================================
__device__ __forceinline__ unsigned pack_bf16(float lo_elem, float hi_elem) {
    unsigned w;
    asm("cvt.rn.bf16x2.f32 %0, %1, %2;" : "=r"(w) : "f"(hi_elem), "f"(lo_elem));
    return w;
}
__device__ __forceinline__ float bfw_lo(unsigned w) { return __uint_as_float(w << 16); }
__device__ __forceinline__ float bfw_hi(unsigned w) { return __uint_as_float(w & 0xFFFF0000u); }

__device__ __forceinline__ void mma_bf16(float* c, const unsigned* a, const unsigned* b) {
    asm volatile("mma.sync.aligned.m16n8k16.row.col.f32.bf16.bf16.f32 "
        "{%0,%1,%2,%3}, {%4,%5,%6,%7}, {%8,%9}, {%0,%1,%2,%3};"
        : "+f"(c[0]), "+f"(c[1]), "+f"(c[2]), "+f"(c[3])
        : "r"(a[0]), "r"(a[1]), "r"(a[2]), "r"(a[3]), "r"(b[0]), "r"(b[1]));
}

// split a float4 (4 consecutive elems) into 2 packed hi words + 2 lo words
__device__ __forceinline__ void split4(float4 v, uint2& hi, uint2& lo) {
    unsigned h0 = pack_bf16(v.x, v.y);
    unsigned h1 = pack_bf16(v.z, v.w);
    hi = make_uint2(h0, h1);
    lo = make_uint2(pack_bf16(v.x - bfw_lo(h0), v.y - bfw_hi(h0)),
                    pack_bf16(v.z - bfw_lo(h1), v.w - bfw_hi(h1)));
}

// =====================================================================
// Stage A: fused dual projection via split-bf16 m16n8k16 (3-term).
// CTA tile 64M x 64N, k-chunks of 32 (= 2 k16 chunks). 8 warps =
// 4(M) x 2(N), each warp m16 x n32. Packed hi/lo planes, XW=20 word
// stride -> conflict-free fragment gathers (gid*20+tig distinct mod 32).
// =====================================================================
#define XW 20
#define PROJ_SMEM_BYTES (6*64*XW*4)

__global__ void __launch_bounds__(256) proj_kernel(
    const float* __restrict__ X,
    const float* __restrict__ Wh, const float* __restrict__ Wz,
    const float* __restrict__ bh, const float* __restrict__ bz,
    float* __restrict__ owh, float* __restrict__ owz)
{
    extern __shared__ unsigned psw[];
    unsigned* Xh  = psw;
    unsigned* Xl  = psw + 64*XW;
    unsigned* Whh = psw + 2*64*XW;
    unsigned* Whl = psw + 3*64*XW;
    unsigned* Wzh = psw + 4*64*XW;
    unsigned* Wzl = psw + 5*64*XW;

    const int tid  = threadIdx.x;
    const int n0   = blockIdx.x * 64;
    const long m0  = (long)blockIdx.y * 64;
    const int lane = tid & 31;
    const int warp = tid >> 5;
    const int wm   = (warp & 3) * 16;
    const int wn   = (warp >> 2) * 32;
    const int gid  = lane >> 2;
    const int tig  = lane & 3;

    float ch[4][4], cz[4][4];
#pragma unroll
    for (int t = 0; t < 4; t++)
#pragma unroll
        for (int i = 0; i < 4; i++) { ch[t][i] = 0.f; cz[t][i] = 0.f; }

    for (int k0 = 0; k0 < 512; k0 += 32) {
        __syncthreads();
#pragma unroll
        for (int q = 0; q < 2; q++) {
            int idx  = tid + 256*q;
            int row  = idx >> 3;
            int col  = (idx & 7) * 4;      // element offset in k-chunk
            int colw = (idx & 7) * 2;      // word offset
            uint2 hi, lo;
            split4(*(const float4*)&X [(m0 + row)*512 + k0 + col], hi, lo);
            *(uint2*)&Xh[row*XW + colw] = hi;
            *(uint2*)&Xl[row*XW + colw] = lo;
            split4(*(const float4*)&Wh[(long)(n0 + row)*512 + k0 + col], hi, lo);
            *(uint2*)&Whh[row*XW + colw] = hi;
            *(uint2*)&Whl[row*XW + colw] = lo;
            split4(*(const float4*)&Wz[(long)(n0 + row)*512 + k0 + col], hi, lo);
            *(uint2*)&Wzh[row*XW + colw] = hi;
            *(uint2*)&Wzl[row*XW + colw] = lo;
        }
        __syncthreads();

#pragma unroll
        for (int kc = 0; kc < 2; kc++) {
            unsigned ahi[4], alo[4];
            {
                int ra = (wm + gid    )*XW + kc*8 + tig;
                int rb = (wm + gid + 8)*XW + kc*8 + tig;
                ahi[0] = Xh[ra];     ahi[1] = Xh[rb];
                ahi[2] = Xh[ra + 4]; ahi[3] = Xh[rb + 4];
                alo[0] = Xl[ra];     alo[1] = Xl[rb];
                alo[2] = Xl[ra + 4]; alo[3] = Xl[rb + 4];
            }
#pragma unroll
            for (int t = 0; t < 4; t++) {
                const int nn = (wn + t*8 + gid)*XW + kc*8 + tig;
                unsigned bhh[2], bhl[2], bzh[2], bzl[2];
                bhh[0] = Whh[nn]; bhh[1] = Whh[nn + 4];
                bhl[0] = Whl[nn]; bhl[1] = Whl[nn + 4];
                bzh[0] = Wzh[nn]; bzh[1] = Wzh[nn + 4];
                bzl[0] = Wzl[nn]; bzl[1] = Wzl[nn + 4];
                mma_bf16(ch[t], ahi, bhh);
                mma_bf16(ch[t], ahi, bhl);
                mma_bf16(ch[t], alo, bhh);
                mma_bf16(cz[t], ahi, bzh);
                mma_bf16(cz[t], ahi, bzl);
                mma_bf16(cz[t], alo, bzh);
            }
        }
    }

    // epilogue: m16n8 C layout identical to previous version
#pragma unroll
    for (int t = 0; t < 4; t++) {
        int colg = n0 + wn + t*8 + tig*2;
        float bh0 = bh[colg], bh1 = bh[colg + 1];
        float bz0 = bz[colg], bz1 = bz[colg + 1];
        long r0 = (m0 + wm + gid    )*512 + colg;
        long r1 = (m0 + wm + gid + 8)*512 + colg;
        owh[r0]     = ch[t][0] + bh0;
        owh[r0 + 1] = ch[t][1] + bh1;
        owh[r1]     = ch[t][2] + bh0;
        owh[r1 + 1] = ch[t][3] + bh1;
        owz[r0]     = cz[t][0] + bz0;
        owz[r0 + 1] = cz[t][1] + bz1;
        owz[r1]     = cz[t][2] + bz0;
        owz[r1 + 1] = cz[t][3] + bz1;
    }
}

// =====================================================================
// Stage B: single-group persistent scan (round-10/11 proven geometry)
// with per-CTA release-flag sync replacing the atomic-counter barrier.
//   publish: __syncthreads(); tid0 st.release.gpu myflag = phase#
//   poll   : lanes 0..15 ld.acquire.gpu of all 16 group flags (1 sector)
//            + __all_sync, per-warp independent
// =====================================================================
#define UPS 260
#define UPLANE (32*UPS)
#define BPLANE (8*UPS)
#define OFF_UZH 0
#define OFF_UZL (OFF_UZH + UPLANE)
#define OFF_UHH (OFF_UZL + UPLANE)
#define OFF_UHL (OFF_UHH + UPLANE)
#define OFF_BH  (OFF_UHL + UPLANE)
#define OFF_BL  (OFF_BH + BPLANE)
#define OFF_RED (OFF_BL + BPLANE)
#define SCAN_SMEM_WORDS (OFF_RED + 8*264)
#define SCAN_SMEM_BYTES (SCAN_SMEM_WORDS*4)

__device__ __forceinline__ void wait_flags(const unsigned int* fgrp, unsigned tgt, int lane)
{
    const unsigned int* fp = fgrp + (lane & 15);
    unsigned v;
    do {
        asm volatile("ld.acquire.gpu.global.u32 %0, [%1];" : "=r"(v) : "l"(fp) : "memory");
    } while (!__all_sync(0xFFFFFFFFu, v >= tgt));
}

__device__ __forceinline__ void publish_flag(unsigned int* myflag, unsigned val)
{
    asm volatile("st.release.gpu.global.u32 [%0], %1;" :: "l"(myflag), "r"(val) : "memory");
}

__device__ __forceinline__ void stage_bf16(unsigned* __restrict__ Bh,
                                           unsigned* __restrict__ Bl,
                                           const float* __restrict__ src,
                                           int warp, int lane)
{
#pragma unroll
    for (int r = 0; r < 4; r++) {
        int q = lane + 32*r;            // 0..127
        int b = q >> 4;                 // 0..7
        int quad = q & 15;
        float4 v = __ldcg((const float4*)(src + b*512 + (warp << 6) + quad*4));
        unsigned h0 = pack_bf16(v.x, v.y);
        unsigned h1 = pack_bf16(v.z, v.w);
        unsigned l0 = pack_bf16(v.x - bfw_lo(h0), v.y - bfw_hi(h0));
        unsigned l1 = pack_bf16(v.z - bfw_lo(h1), v.w - bfw_hi(h1));
        int k2 = (warp << 5) + quad*2;
        *(uint2*)(Bh + b*UPS + k2) = make_uint2(h0, h1);
        *(uint2*)(Bl + b*UPS + k2) = make_uint2(l0, l1);
    }
    __syncwarp();
}

__device__ __forceinline__ void gemm_mma(const unsigned* __restrict__ Bh,
                                         const unsigned* __restrict__ Bl,
                                         const unsigned* __restrict__ Uh,
                                         const unsigned* __restrict__ Ul,
                                         float* __restrict__ red,
                                         int warp, int lane)
{
    const int gid = lane >> 2;
    const int tig = lane & 3;

    float c0[4] = {0.f,0.f,0.f,0.f};
    float c1[4] = {0.f,0.f,0.f,0.f};

#pragma unroll
    for (int kc = 0; kc < 4; kc++) {
        const int k2 = (warp << 5) + (kc << 3) + tig;
        unsigned bhf[2], blf[2];
        bhf[0] = Bh[gid*UPS + k2];  bhf[1] = Bh[gid*UPS + k2 + 4];
        blf[0] = Bl[gid*UPS + k2];  blf[1] = Bl[gid*UPS + k2 + 4];

#pragma unroll
        for (int iw = 0; iw < 2; iw++) {
            const int r0 = iw*16 + gid;
            unsigned ah[4], al[4];
            ah[0] = Uh[(r0    )*UPS + k2    ];
            ah[1] = Uh[(r0 + 8)*UPS + k2    ];
            ah[2] = Uh[(r0    )*UPS + k2 + 4];
            ah[3] = Uh[(r0 + 8)*UPS + k2 + 4];
            al[0] = Ul[(r0    )*UPS + k2    ];
            al[1] = Ul[(r0 + 8)*UPS + k2    ];
            al[2] = Ul[(r0    )*UPS + k2 + 4];
            al[3] = Ul[(r0 + 8)*UPS + k2 + 4];
            float* cc = iw ? c1 : c0;
            mma_bf16(cc, ah, bhf);
            mma_bf16(cc, ah, blf);
            mma_bf16(cc, al, bhf);
        }
    }

    float* rp = red + warp*264;
#pragma unroll
    for (int iw = 0; iw < 2; iw++) {
        const float* cc = iw ? c1 : c0;
        int ia = iw*16 + gid;
        rp[(2*tig    )*33 + ia    ] = cc[0];
        rp[(2*tig + 1)*33 + ia    ] = cc[1];
        rp[(2*tig    )*33 + ia + 8] = cc[2];
        rp[(2*tig + 1)*33 + ia + 8] = cc[3];
    }
}

__global__ void __launch_bounds__(256) scan_kernel(
    const float* __restrict__ wh, const float* __restrict__ wz,
    const float* __restrict__ Uh, const float* __restrict__ Uz,
    float* __restrict__ out,
    float* __restrict__ hT, float* __restrict__ zhT,
    unsigned int* __restrict__ flags)
{
    extern __shared__ float sm[];
    unsigned* UZH = (unsigned*)(sm + OFF_UZH);
    unsigned* UZL = (unsigned*)(sm + OFF_UZL);
    unsigned* UHH = (unsigned*)(sm + OFF_UHH);
    unsigned* UHL = (unsigned*)(sm + OFF_UHL);
    unsigned* BH  = (unsigned*)(sm + OFF_BH);
    unsigned* BL  = (unsigned*)(sm + OFF_BL);
    float*    red = sm + OFF_RED;

    const int tid  = threadIdx.x;
    const int s    = blockIdx.x & 15;   // H slice
    const int g    = blockIdx.x >> 4;   // group 0..7
    const int i0   = s * 32;
    const int warp = tid >> 5;
    const int lane = tid & 31;

    // one-time U pre-split into packed bf16 hi/lo planes
    for (int idx = tid; idx < 32*256; idx += 256) {
        int i  = idx >> 8;
        int j2 = idx & 255;
        float2 uz = *(const float2*)&Uz[(i0 + i)*512 + 2*j2];
        unsigned h = pack_bf16(uz.x, uz.y);
        UZH[i*UPS + j2] = h;
        UZL[i*UPS + j2] = pack_bf16(uz.x - bfw_lo(h), uz.y - bfw_hi(h));
        float2 uh = *(const float2*)&Uh[(i0 + i)*512 + 2*j2];
        unsigned h2 = pack_bf16(uh.x, uh.y);
        UHH[i*UPS + j2] = h2;
        UHL[i*UPS + j2] = pack_bf16(uh.x - bfw_lo(h2), uh.y - bfw_hi(h2));
    }
    __syncthreads();

    const int bl = tid >> 5;
    const int il = tid & 31;
    const int jg = i0 + il;

    float* hTg  = hT  + g*4096;
    float* zhTg = zhT + g*4096;
    unsigned int* fgrp   = flags + g*16;
    unsigned int* myflag = flags + g*16 + s;

    float h_own = 0.f;

    for (int t = 0; t < T_; t++) {
        long base = ((long)(t*B_) + g*8 + bl)*(long)H_ + jg;
        float wzv = __ldcg(wz + base);
        float whv = __ldcg(wh + base);

        // ================= phase Z =================
        wait_flags(fgrp, 2u*(unsigned)t, lane);
        stage_bf16(BH, BL, hTg, warp, lane);
        gemm_mma(BH, BL, UZH, UZL, red, warp, lane);
        __syncthreads();

        float sum = 0.f;
#pragma unroll
        for (int w = 0; w < 8; w++) sum += red[w*264 + bl*33 + il];
        float z  = __fdividef(1.f, 1.f + __expf(-(sum + wzv)));
        float zh = z * h_own;
        zhTg[bl*512 + jg] = zh;
        __syncthreads();
        if (tid == 0) publish_flag(myflag, 2u*(unsigned)t + 1u);

        // ================= phase H =================
        wait_flags(fgrp, 2u*(unsigned)t + 1u, lane);
        stage_bf16(BH, BL, zhTg, warp, lane);
        gemm_mma(BH, BL, UHH, UHL, red, warp, lane);
        __syncthreads();

        float sum2 = 0.f;
#pragma unroll
        for (int w = 0; w < 8; w++) sum2 += red[w*264 + bl*33 + il];
        float ahv = sum2 + whv;
        float hc = __fdividef(2.f, 1.f + __expf(-2.f*ahv)) - 1.f;
        float hn = zh + (1.f - z)*hc;
        h_own = hn;
        hTg[bl*512 + jg] = hn;
        out[base] = hn;
        __syncthreads();
        if (tid == 0) publish_flag(myflag, 2u*(unsigned)t + 2u);
    }
}

// =====================================================================
extern "C" void kernel_launch(void* const* d_in, const int* in_sizes, int n_in,
                              void* d_out, int out_size)
{
    const float* x   = (const float*)d_in[0];
    const float* Wh0 = (const float*)d_in[1];
    const float* bh0 = (const float*)d_in[2];
    const float* Wz0 = (const float*)d_in[3];
    const float* bz0 = (const float*)d_in[4];
    const float* Uh0 = (const float*)d_in[5];
    const float* Uz0 = (const float*)d_in[6];
    const float* Wh1 = (const float*)d_in[7];
    const float* bh1 = (const float*)d_in[8];
    const float* Wz1 = (const float*)d_in[9];
    const float* bz1 = (const float*)d_in[10];
    const float* Uh1 = (const float*)d_in[11];
    const float* Uz1 = (const float*)d_in[12];
    float* out = (float*)d_out;

    float *p_wh, *p_wz, *p_h1, *p_hT, *p_zhT;
    unsigned int* p_flags;
    cudaGetSymbolAddress((void**)&p_wh, g_wh);
    cudaGetSymbolAddress((void**)&p_wz, g_wz);
    cudaGetSymbolAddress((void**)&p_h1, g_h1);
    cudaGetSymbolAddress((void**)&p_hT, g_hT);
    cudaGetSymbolAddress((void**)&p_zhT, g_zhT);
    cudaGetSymbolAddress((void**)&p_flags, g_flags);

    cudaFuncSetAttribute(proj_kernel,
                         cudaFuncAttributeMaxDynamicSharedMemorySize, PROJ_SMEM_BYTES);
    cudaFuncSetAttribute(scan_kernel,
                         cudaFuncAttributeMaxDynamicSharedMemorySize, SCAN_SMEM_BYTES);

    dim3 pgrid(8, 2000);

    // ---- Layer 0 ----
    proj_kernel<<<pgrid, 256, PROJ_SMEM_BYTES>>>(x, Wh0, Wz0, bh0, bz0, p_wh, p_wz);
    cudaMemsetAsync(p_hT, 0, 8*8*512*sizeof(float));
    cudaMemsetAsync(p_flags, 0, 8*16*sizeof(unsigned int));
    scan_kernel<<<128, 256, SCAN_SMEM_BYTES>>>(p_wh, p_wz, Uh0, Uz0,
                                               p_h1, p_hT, p_zhT, p_flags);

    // ---- Layer 1 ----
    proj_kernel<<<pgrid, 256, PROJ_SMEM_BYTES>>>(p_h1, Wh1, Wz1, bh1, bz1, p_wh, p_wz);
    cudaMemsetAsync(p_hT, 0, 8*8*512*sizeof(float));
    cudaMemsetAsync(p_flags, 0, 8*16*sizeof(unsigned int));
    scan_kernel<<<128, 256, SCAN_SMEM_BYTES>>>(p_wh, p_wz, Uh1, Uz1,
                                               out, p_hT, p_zhT, p_flags);
}

// round 13
// speedup vs baseline: 2.8271x; 2.8271x over previous
#include <cuda_runtime.h>
#include <math.h>

#define T_ 2000
#define B_ 64
#define H_ 512
#define TB_ (T_*B_)

// ---- scratch ----
__device__ float g_wh[TB_*H_];
__device__ float g_wz[TB_*H_];
__device__ float g_h1[TB_*H_];
__device__ float g_hT[8*8*512];      // [group][b][512 j]
__device__ float g_zhT[8*8*512];     // [group][b][512 j]
__device__ unsigned int g_bar[8];    // single hot counter per group (proven)

// =====================================================================
// bf16 split helpers (shared by proj + scan)
// word packs: even elem -> low 16, odd elem -> high 16
// =====================================================================
__device__ __forceinline__ unsigned pack_bf16(float lo_elem, float hi_elem) {
    unsigned w;
    asm("cvt.rn.bf16x2.f32 %0, %1, %2;" : "=r"(w) : "f"(hi_elem), "f"(lo_elem));
    return w;
}
__device__ __forceinline__ float bfw_lo(unsigned w) { return __uint_as_float(w << 16); }
__device__ __forceinline__ float bfw_hi(unsigned w) { return __uint_as_float(w & 0xFFFF0000u); }

__device__ __forceinline__ void mma_bf16(float* c, const unsigned* a, const unsigned* b) {
    asm volatile("mma.sync.aligned.m16n8k16.row.col.f32.bf16.bf16.f32 "
        "{%0,%1,%2,%3}, {%4,%5,%6,%7}, {%8,%9}, {%0,%1,%2,%3};"
        : "+f"(c[0]), "+f"(c[1]), "+f"(c[2]), "+f"(c[3])
        : "r"(a[0]), "r"(a[1]), "r"(a[2]), "r"(a[3]), "r"(b[0]), "r"(b[1]));
}

__device__ __forceinline__ void split4(float4 v, uint2& hi, uint2& lo) {
    unsigned h0 = pack_bf16(v.x, v.y);
    unsigned h1 = pack_bf16(v.z, v.w);
    hi = make_uint2(h0, h1);
    lo = make_uint2(pack_bf16(v.x - bfw_lo(h0), v.y - bfw_hi(h0)),
                    pack_bf16(v.z - bfw_lo(h1), v.w - bfw_hi(h1)));
}

// =====================================================================
// Stage A: fused dual projection via split-bf16 m16n8k16 (3-term).
// CTA tile 64M x 64N, k-chunks of 32 (= 2 k16). 8 warps = 4(M) x 2(N),
// each warp m16 x n32. Packed hi/lo planes, XW=20 word stride.
// (round-12 version — retained; regression was attributed to scan sync)
// =====================================================================
#define XW 20
#define PROJ_SMEM_BYTES (6*64*XW*4)

__global__ void __launch_bounds__(256) proj_kernel(
    const float* __restrict__ X,
    const float* __restrict__ Wh, const float* __restrict__ Wz,
    const float* __restrict__ bh, const float* __restrict__ bz,
    float* __restrict__ owh, float* __restrict__ owz)
{
    extern __shared__ unsigned psw[];
    unsigned* Xh  = psw;
    unsigned* Xl  = psw + 64*XW;
    unsigned* Whh = psw + 2*64*XW;
    unsigned* Whl = psw + 3*64*XW;
    unsigned* Wzh = psw + 4*64*XW;
    unsigned* Wzl = psw + 5*64*XW;

    const int tid  = threadIdx.x;
    const int n0   = blockIdx.x * 64;
    const long m0  = (long)blockIdx.y * 64;
    const int lane = tid & 31;
    const int warp = tid >> 5;
    const int wm   = (warp & 3) * 16;
    const int wn   = (warp >> 2) * 32;
    const int gid  = lane >> 2;
    const int tig  = lane & 3;

    float ch[4][4], cz[4][4];
#pragma unroll
    for (int t = 0; t < 4; t++)
#pragma unroll
        for (int i = 0; i < 4; i++) { ch[t][i] = 0.f; cz[t][i] = 0.f; }

    for (int k0 = 0; k0 < 512; k0 += 32) {
        __syncthreads();
#pragma unroll
        for (int q = 0; q < 2; q++) {
            int idx  = tid + 256*q;
            int row  = idx >> 3;
            int col  = (idx & 7) * 4;
            int colw = (idx & 7) * 2;
            uint2 hi, lo;
            split4(*(const float4*)&X [(m0 + row)*512 + k0 + col], hi, lo);
            *(uint2*)&Xh[row*XW + colw] = hi;
            *(uint2*)&Xl[row*XW + colw] = lo;
            split4(*(const float4*)&Wh[(long)(n0 + row)*512 + k0 + col], hi, lo);
            *(uint2*)&Whh[row*XW + colw] = hi;
            *(uint2*)&Whl[row*XW + colw] = lo;
            split4(*(const float4*)&Wz[(long)(n0 + row)*512 + k0 + col], hi, lo);
            *(uint2*)&Wzh[row*XW + colw] = hi;
            *(uint2*)&Wzl[row*XW + colw] = lo;
        }
        __syncthreads();

#pragma unroll
        for (int kc = 0; kc < 2; kc++) {
            unsigned ahi[4], alo[4];
            {
                int ra = (wm + gid    )*XW + kc*8 + tig;
                int rb = (wm + gid + 8)*XW + kc*8 + tig;
                ahi[0] = Xh[ra];     ahi[1] = Xh[rb];
                ahi[2] = Xh[ra + 4]; ahi[3] = Xh[rb + 4];
                alo[0] = Xl[ra];     alo[1] = Xl[rb];
                alo[2] = Xl[ra + 4]; alo[3] = Xl[rb + 4];
            }
#pragma unroll
            for (int t = 0; t < 4; t++) {
                const int nn = (wn + t*8 + gid)*XW + kc*8 + tig;
                unsigned bhh[2], bhl[2], bzh[2], bzl[2];
                bhh[0] = Whh[nn]; bhh[1] = Whh[nn + 4];
                bhl[0] = Whl[nn]; bhl[1] = Whl[nn + 4];
                bzh[0] = Wzh[nn]; bzh[1] = Wzh[nn + 4];
                bzl[0] = Wzl[nn]; bzl[1] = Wzl[nn + 4];
                mma_bf16(ch[t], ahi, bhh);
                mma_bf16(ch[t], ahi, bhl);
                mma_bf16(ch[t], alo, bhh);
                mma_bf16(cz[t], ahi, bzh);
                mma_bf16(cz[t], ahi, bzl);
                mma_bf16(cz[t], alo, bzh);
            }
        }
    }

#pragma unroll
    for (int t = 0; t < 4; t++) {
        int colg = n0 + wn + t*8 + tig*2;
        float bh0 = bh[colg], bh1 = bh[colg + 1];
        float bz0 = bz[colg], bz1 = bz[colg + 1];
        long r0 = (m0 + wm + gid    )*512 + colg;
        long r1 = (m0 + wm + gid + 8)*512 + colg;
        owh[r0]     = ch[t][0] + bh0;
        owh[r0 + 1] = ch[t][1] + bh1;
        owh[r1]     = ch[t][2] + bh0;
        owh[r1 + 1] = ch[t][3] + bh1;
        owz[r0]     = cz[t][0] + bz0;
        owz[r0 + 1] = cz[t][1] + bz1;
        owz[r1]     = cz[t][2] + bz0;
        owz[r1 + 1] = cz[t][3] + bz1;
    }
}

// =====================================================================
// Stage B: single-group persistent scan — round-10/11 PROVEN version,
// VERBATIM (atomic counter + single-hot-word acquire poll, 23.29ms).
// =====================================================================
#define UPS 260
#define UPLANE (32*UPS)
#define BPLANE (8*UPS)
#define OFF_UZH 0
#define OFF_UZL (OFF_UZH + UPLANE)
#define OFF_UHH (OFF_UZL + UPLANE)
#define OFF_UHL (OFF_UHH + UPLANE)
#define OFF_BH  (OFF_UHL + UPLANE)
#define OFF_BL  (OFF_BH + BPLANE)
#define OFF_RED (OFF_BL + BPLANE)
#define SCAN_SMEM_WORDS (OFF_RED + 8*264)
#define SCAN_SMEM_BYTES (SCAN_SMEM_WORDS*4)

__device__ __forceinline__ void wait_flag(const unsigned int* f, unsigned tgt)
{
    unsigned v;
    do {
        asm volatile("ld.global.acquire.gpu.u32 %0, [%1];" : "=r"(v) : "l"(f));
    } while (v < tgt);
}

__device__ __forceinline__ void stage_bf16(unsigned* __restrict__ Bh,
                                           unsigned* __restrict__ Bl,
                                           const float* __restrict__ src,
                                           int warp, int lane)
{
#pragma unroll
    for (int r = 0; r < 4; r++) {
        int q = lane + 32*r;            // 0..127
        int b = q >> 4;                 // 0..7
        int quad = q & 15;
        float4 v = __ldcg((const float4*)(src + b*512 + (warp << 6) + quad*4));
        unsigned h0 = pack_bf16(v.x, v.y);
        unsigned h1 = pack_bf16(v.z, v.w);
        unsigned l0 = pack_bf16(v.x - bfw_lo(h0), v.y - bfw_hi(h0));
        unsigned l1 = pack_bf16(v.z - bfw_lo(h1), v.w - bfw_hi(h1));
        int k2 = (warp << 5) + quad*2;
        *(uint2*)(Bh + b*UPS + k2) = make_uint2(h0, h1);
        *(uint2*)(Bl + b*UPS + k2) = make_uint2(l0, l1);
    }
    __syncwarp();
}

__device__ __forceinline__ void gemm_mma(const unsigned* __restrict__ Bh,
                                         const unsigned* __restrict__ Bl,
                                         const unsigned* __restrict__ Uh,
                                         const unsigned* __restrict__ Ul,
                                         float* __restrict__ red,
                                         int warp, int lane)
{
    const int gid = lane >> 2;
    const int tig = lane & 3;

    float c0[4] = {0.f,0.f,0.f,0.f};
    float c1[4] = {0.f,0.f,0.f,0.f};

#pragma unroll
    for (int kc = 0; kc < 4; kc++) {
        const int k2 = (warp << 5) + (kc << 3) + tig;
        unsigned bhf[2], blf[2];
        bhf[0] = Bh[gid*UPS + k2];  bhf[1] = Bh[gid*UPS + k2 + 4];
        blf[0] = Bl[gid*UPS + k2];  blf[1] = Bl[gid*UPS + k2 + 4];

#pragma unroll
        for (int iw = 0; iw < 2; iw++) {
            const int r0 = iw*16 + gid;
            unsigned ah[4], al[4];
            ah[0] = Uh[(r0    )*UPS + k2    ];
            ah[1] = Uh[(r0 + 8)*UPS + k2    ];
            ah[2] = Uh[(r0    )*UPS + k2 + 4];
            ah[3] = Uh[(r0 + 8)*UPS + k2 + 4];
            al[0] = Ul[(r0    )*UPS + k2    ];
            al[1] = Ul[(r0 + 8)*UPS + k2    ];
            al[2] = Ul[(r0    )*UPS + k2 + 4];
            al[3] = Ul[(r0 + 8)*UPS + k2 + 4];
            float* cc = iw ? c1 : c0;
            mma_bf16(cc, ah, bhf);
            mma_bf16(cc, ah, blf);
            mma_bf16(cc, al, bhf);
        }
    }

    float* rp = red + warp*264;
#pragma unroll
    for (int iw = 0; iw < 2; iw++) {
        const float* cc = iw ? c1 : c0;
        int ia = iw*16 + gid;
        rp[(2*tig    )*33 + ia    ] = cc[0];
        rp[(2*tig + 1)*33 + ia    ] = cc[1];
        rp[(2*tig    )*33 + ia + 8] = cc[2];
        rp[(2*tig + 1)*33 + ia + 8] = cc[3];
    }
}

__global__ void __launch_bounds__(256) scan_kernel(
    const float* __restrict__ wh, const float* __restrict__ wz,
    const float* __restrict__ Uh, const float* __restrict__ Uz,
    float* __restrict__ out,
    float* __restrict__ hT, float* __restrict__ zhT,
    unsigned int* __restrict__ bar)
{
    extern __shared__ float sm[];
    unsigned* UZH = (unsigned*)(sm + OFF_UZH);
    unsigned* UZL = (unsigned*)(sm + OFF_UZL);
    unsigned* UHH = (unsigned*)(sm + OFF_UHH);
    unsigned* UHL = (unsigned*)(sm + OFF_UHL);
    unsigned* BH  = (unsigned*)(sm + OFF_BH);
    unsigned* BL  = (unsigned*)(sm + OFF_BL);
    float*    red = sm + OFF_RED;

    const int tid  = threadIdx.x;
    const int s    = blockIdx.x & 15;   // H slice
    const int g    = blockIdx.x >> 4;   // group 0..7
    const int i0   = s * 32;
    const int warp = tid >> 5;
    const int lane = tid & 31;

    for (int idx = tid; idx < 32*256; idx += 256) {
        int i  = idx >> 8;
        int j2 = idx & 255;
        float2 uz = *(const float2*)&Uz[(i0 + i)*512 + 2*j2];
        unsigned h = pack_bf16(uz.x, uz.y);
        UZH[i*UPS + j2] = h;
        UZL[i*UPS + j2] = pack_bf16(uz.x - bfw_lo(h), uz.y - bfw_hi(h));
        float2 uh = *(const float2*)&Uh[(i0 + i)*512 + 2*j2];
        unsigned h2 = pack_bf16(uh.x, uh.y);
        UHH[i*UPS + j2] = h2;
        UHL[i*UPS + j2] = pack_bf16(uh.x - bfw_lo(h2), uh.y - bfw_hi(h2));
    }
    __syncthreads();

    const int bl = tid >> 5;
    const int il = tid & 31;
    const int jg = i0 + il;

    float* hTg  = hT  + g*4096;
    float* zhTg = zhT + g*4096;
    unsigned int* barg = bar + g;

    float h_own = 0.f;

    for (int t = 0; t < T_; t++) {
        long base = ((long)(t*B_) + g*8 + bl)*(long)H_ + jg;
        float wzv = __ldcg(wz + base);
        float whv = __ldcg(wh + base);

        // ================= phase Z =================
        wait_flag(barg, 32u*(unsigned)t);
        stage_bf16(BH, BL, hTg, warp, lane);
        gemm_mma(BH, BL, UZH, UZL, red, warp, lane);
        __syncthreads();

        float sum = 0.f;
#pragma unroll
        for (int w = 0; w < 8; w++) sum += red[w*264 + bl*33 + il];
        float z  = __fdividef(1.f, 1.f + __expf(-(sum + wzv)));
        float zh = z * h_own;
        zhTg[bl*512 + jg] = zh;
        __syncthreads();
        if (tid == 0) { __threadfence(); atomicAdd(barg, 1u); }

        // ================= phase H =================
        wait_flag(barg, 32u*(unsigned)t + 16u);
        stage_bf16(BH, BL, zhTg, warp, lane);
        gemm_mma(BH, BL, UHH, UHL, red, warp, lane);
        __syncthreads();

        float sum2 = 0.f;
#pragma unroll
        for (int w = 0; w < 8; w++) sum2 += red[w*264 + bl*33 + il];
        float ahv = sum2 + whv;
        float hc = __fdividef(2.f, 1.f + __expf(-2.f*ahv)) - 1.f;
        float hn = zh + (1.f - z)*hc;
        h_own = hn;
        hTg[bl*512 + jg] = hn;
        out[base] = hn;
        __syncthreads();
        if (tid == 0) { __threadfence(); atomicAdd(barg, 1u); }
    }
}

// =====================================================================
extern "C" void kernel_launch(void* const* d_in, const int* in_sizes, int n_in,
                              void* d_out, int out_size)
{
    const float* x   = (const float*)d_in[0];
    const float* Wh0 = (const float*)d_in[1];
    const float* bh0 = (const float*)d_in[2];
    const float* Wz0 = (const float*)d_in[3];
    const float* bz0 = (const float*)d_in[4];
    const float* Uh0 = (const float*)d_in[5];
    const float* Uz0 = (const float*)d_in[6];
    const float* Wh1 = (const float*)d_in[7];
    const float* bh1 = (const float*)d_in[8];
    const float* Wz1 = (const float*)d_in[9];
    const float* bz1 = (const float*)d_in[10];
    const float* Uh1 = (const float*)d_in[11];
    const float* Uz1 = (const float*)d_in[12];
    float* out = (float*)d_out;

    float *p_wh, *p_wz, *p_h1, *p_hT, *p_zhT;
    unsigned int* p_bar;
    cudaGetSymbolAddress((void**)&p_wh, g_wh);
    cudaGetSymbolAddress((void**)&p_wz, g_wz);
    cudaGetSymbolAddress((void**)&p_h1, g_h1);
    cudaGetSymbolAddress((void**)&p_hT, g_hT);
    cudaGetSymbolAddress((void**)&p_zhT, g_zhT);
    cudaGetSymbolAddress((void**)&p_bar, g_bar);

    cudaFuncSetAttribute(proj_kernel,
                         cudaFuncAttributeMaxDynamicSharedMemorySize, PROJ_SMEM_BYTES);
    cudaFuncSetAttribute(scan_kernel,
                         cudaFuncAttributeMaxDynamicSharedMemorySize, SCAN_SMEM_BYTES);

    dim3 pgrid(8, 2000);

    // ---- Layer 0 ----
    proj_kernel<<<pgrid, 256, PROJ_SMEM_BYTES>>>(x, Wh0, Wz0, bh0, bz0, p_wh, p_wz);
    cudaMemsetAsync(p_hT, 0, 8*8*512*sizeof(float));
    cudaMemsetAsync(p_bar, 0, 8*sizeof(unsigned int));
    scan_kernel<<<128, 256, SCAN_SMEM_BYTES>>>(p_wh, p_wz, Uh0, Uz0,
                                               p_h1, p_hT, p_zhT, p_bar);

    // ---- Layer 1 ----
    proj_kernel<<<pgrid, 256, PROJ_SMEM_BYTES>>>(p_h1, Wh1, Wz1, bh1, bz1, p_wh, p_wz);
    cudaMemsetAsync(p_hT, 0, 8*8*512*sizeof(float));
    cudaMemsetAsync(p_bar, 0, 8*sizeof(unsigned int));
    scan_kernel<<<128, 256, SCAN_SMEM_BYTES>>>(p_wh, p_wz, Uh1, Uz1,
                                               out, p_hT, p_zhT, p_bar);
}